// round 8
// baseline (speedup 1.0000x reference)
#include <cuda_runtime.h>
#include <math_constants.h>

// Cumulative max along H for x[B=32, C=1, H=1024, W=2048] fp32.
// Single streaming pass: 256 MB read + 256 MB write (the traffic floor).
//
// R6: scalar-float columns -> 65536 threads (2048 blocks x 32),
// 13.8 warps/SM (2x R5's TLP) so the SMSP arbiter always has an
// independent warp to issue loads from while another sits in its
// dependent fmax->STG window. One LDG.32/STG.32 per warp = exactly one
// 128 B line, same per-byte wavefront cost as float2. Ring-buffer
// pipeline depth U=32 keeps 128 B/thread (8 MB chip-wide) continuously
// in flight. Streaming cache hints: no byte is reused.

static constexpr int B = 32;
static constexpr int H = 1024;
static constexpr int W = 2048;
static constexpr int NCOLS = B * W;          // 65536 threads
static constexpr int U = 32;                 // pipeline depth (scalar loads)
static constexpr int NCHUNK = H / U;         // 32 chunks

__global__ void __launch_bounds__(32)
cummax_h_kernel(const float* __restrict__ x, float* __restrict__ out) {
    int c = blockIdx.x * blockDim.x + threadIdx.x;   // 0 .. NCOLS-1

    int b = c >> 11;           // c / 2048
    int w = c & (W - 1);       // c % 2048

    const float* __restrict__ p = x   + (size_t)b * H * W + w;
    float*       __restrict__ q = out + (size_t)b * H * W + w;

    float m = -CUDART_INF_F;

    float buf[U];

    // Prologue: fill the pipeline with rows 0..U-1.
    #pragma unroll
    for (int i = 0; i < U; i++)
        buf[i] = __ldcs(p + (size_t)i * W);

    // Steady state: consume row hCur+i while refilling with row hCur+i+U.
    // The refill load is independent of the fmax chain and issues first,
    // so U loads stay in flight continuously with no drain windows.
    for (int cc = 0; cc < NCHUNK - 1; cc++) {
        int hCur = cc * U;
        int hNxt = hCur + U;
        #pragma unroll
        for (int i = 0; i < U; i++) {
            float v = buf[i];
            buf[i] = __ldcs(p + (size_t)(hNxt + i) * W);
            m = fmaxf(m, v);
            __stcs(q + (size_t)(hCur + i) * W, m);
        }
    }

    // Epilogue: drain the last chunk (rows H-U .. H-1).
    {
        int hCur = (NCHUNK - 1) * U;
        #pragma unroll
        for (int i = 0; i < U; i++) {
            m = fmaxf(m, buf[i]);
            __stcs(q + (size_t)(hCur + i) * W, m);
        }
    }
}

extern "C" void kernel_launch(void* const* d_in, const int* in_sizes, int n_in,
                              void* d_out, int out_size) {
    const float* x   = (const float*)d_in[0];
    float*       out = (float*)d_out;

    // 2048 blocks x 32 threads = 65536 threads, one per scalar column.
    cummax_h_kernel<<<NCOLS / 32, 32>>>(x, out);
}